// round 8
// baseline (speedup 1.0000x reference)
#include <cuda_runtime.h>
#include <cstdint>
#include <cstddef>

// Problem constants
#define NB    4096
#define L2DIM 49
#define CDIM  128
#define BAD   324
#define CP    64            // channel pairs (f32x2)
#define NTHR  512

typedef unsigned long long ull;

__device__ __forceinline__ ull ffma2(ull a, ull b, ull c) {
    ull d;
    asm("fma.rn.f32x2 %0, %1, %2, %3;" : "=l"(d) : "l"(a), "l"(b), "l"(c));
    return d;
}
__device__ __forceinline__ ull fmul2(ull a, ull b) {
    ull d;
    asm("mul.rn.f32x2 %0, %1, %2;" : "=l"(d) : "l"(a), "l"(b));
    return d;
}
__device__ __forceinline__ ull fadd2(ull a, ull b) {
    ull d;
    asm("add.rn.f32x2 %0, %1, %2;" : "=l"(d) : "l"(a), "l"(b));
    return d;
}
__device__ __forceinline__ ull pack2(float x) {
    ull d;
    asm("mov.b64 %0, {%1, %1};" : "=l"(d) : "f"(x));
    return d;
}

// ---------------- SMEM layout (232448 B = max dynamic) ----------------
// [0, 165888)        G2s : ull[324][64]   (squared grid; later reused for partials P[4][49][64])
// [165888, 232448)   region2 (66560 B):
//    phase A: Bs ull[49][64] @ +0 (25088) ; As float[49][128] @ +25088 (25088)
//    phase B: Ws ull[4*33][62] dup-weights @ +0 (65472)
#define R2_OFF     165888
#define AS_OFF     (165888 + 25088)
#define WS_STRIDE  62
#define WS_CHUNK   33
#define SMEM_BYTES 232448

__global__ void __launch_bounds__(NTHR, 1)
fused_kernel(const float* __restrict__ X,
             const float* __restrict__ Wto,
             const float* __restrict__ Wf,
             float* __restrict__ Out) {
    extern __shared__ __align__(16) char smem[];
    ull*   G2s = reinterpret_cast<ull*>(smem);
    ull*   Bs  = reinterpret_cast<ull*>(smem + R2_OFF);
    float* As  = reinterpret_cast<float*>(smem + AS_OFF);
    ull*   Ws  = reinterpret_cast<ull*>(smem + R2_OFF);

    const int n    = blockIdx.x;
    const int tid  = threadIdx.x;
    const int wrp  = tid >> 5;
    const int lane = tid & 31;

    // Warp/lane roles (phase A): warp = (strip-group sg, cgroup cgw); lane = (rl, cl)
    const int sg  = wrp >> 2;          // 0..3 : 32-row strip within 128-row chunk
    const int cgw = wrp & 3;           // 0..3 : 16-cpair group
    const int rl  = lane >> 2;         // 0..7 : 4-row sub-strip
    const int cl  = lane & 3;          // 0..3 : 4-cpair sub-group
    const int cpb = cgw * 16 + cl * 4; // first cpair (ull index) owned by this lane

    // ---------- stage Bs: x[n] as ull cpairs (coalesced) ----------
    {
        const ull* Xu = reinterpret_cast<const ull*>(X) + (size_t)n * L2DIM * CP;
        for (int idx = tid; idx < L2DIM * CP; idx += NTHR) Bs[idx] = Xu[idx];
    }

    // ================= Phase A: G2s[ba][cp] = (W_to @ x)^2 =================
    for (int chunk = 0; chunk < 3; chunk++) {
        const int cbase = chunk * 128;
        __syncthreads();   // previous chunk's As readers done (also covers Bs visibility)
        // stage As[i][r] = Wto[(cbase+r)*49 + i], zero-padded beyond row 323
        for (int idx = tid; idx < 128 * L2DIM; idx += NTHR) {
            int r = idx / L2DIM;
            int i = idx - r * L2DIM;
            float v = (cbase + r < BAD) ? Wto[(size_t)(cbase + r) * L2DIM + i] : 0.0f;
            As[i * 128 + r] = v;
        }
        __syncthreads();

        const int strip = cbase + sg * 32;
        if (strip < BAD) {
            ull acc[4][4];
#pragma unroll
            for (int d = 0; d < 4; d++)
#pragma unroll
                for (int k = 0; k < 4; k++) acc[d][k] = 0ull;

            const float* wptr = As + sg * 32 + rl * 4;
            const ull*   xptr = Bs + cpb;
#pragma unroll 7
            for (int i = 0; i < L2DIM; i++) {
                float4 wv = *reinterpret_cast<const float4*>(wptr + i * 128);
                ull w0 = pack2(wv.x), w1 = pack2(wv.y), w2 = pack2(wv.z), w3 = pack2(wv.w);
                ulonglong2 x01 = *reinterpret_cast<const ulonglong2*>(xptr + i * 64);
                ulonglong2 x23 = *reinterpret_cast<const ulonglong2*>(xptr + i * 64 + 2);
                acc[0][0] = ffma2(w0, x01.x, acc[0][0]);
                acc[0][1] = ffma2(w0, x01.y, acc[0][1]);
                acc[0][2] = ffma2(w0, x23.x, acc[0][2]);
                acc[0][3] = ffma2(w0, x23.y, acc[0][3]);
                acc[1][0] = ffma2(w1, x01.x, acc[1][0]);
                acc[1][1] = ffma2(w1, x01.y, acc[1][1]);
                acc[1][2] = ffma2(w1, x23.x, acc[1][2]);
                acc[1][3] = ffma2(w1, x23.y, acc[1][3]);
                acc[2][0] = ffma2(w2, x01.x, acc[2][0]);
                acc[2][1] = ffma2(w2, x01.y, acc[2][1]);
                acc[2][2] = ffma2(w2, x23.x, acc[2][2]);
                acc[2][3] = ffma2(w2, x23.y, acc[2][3]);
                acc[3][0] = ffma2(w3, x01.x, acc[3][0]);
                acc[3][1] = ffma2(w3, x01.y, acc[3][1]);
                acc[3][2] = ffma2(w3, x23.x, acc[3][2]);
                acc[3][3] = ffma2(w3, x23.y, acc[3][3]);
            }
            // square & store to G2s (guard ragged rows)
#pragma unroll
            for (int d = 0; d < 4; d++) {
                int row = strip + rl * 4 + d;
                if (row < BAD) {
                    ulonglong2 v0, v1;
                    v0.x = fmul2(acc[d][0], acc[d][0]);
                    v0.y = fmul2(acc[d][1], acc[d][1]);
                    v1.x = fmul2(acc[d][2], acc[d][2]);
                    v1.y = fmul2(acc[d][3], acc[d][3]);
                    *reinterpret_cast<ulonglong2*>(G2s + (size_t)row * CP + cpb)     = v0;
                    *reinterpret_cast<ulonglong2*>(G2s + (size_t)row * CP + cpb + 2) = v1;
                }
            }
        }
    }

    // ================= Phase B: out[i][cp] = W_from^T @ G2 =================
    // warp = (quarter q, cgroup cgw); lane<28 = (ig, cl): i = ig*7..ig*7+6
    const int  q   = wrp >> 2;        // ba quarter: rows q*81 .. q*81+80
    const int  ig  = lane >> 2;       // 0..7 (only 0..6 active)
    const bool act = (lane < 28);

    ull acc[7][4];
#pragma unroll
    for (int j = 0; j < 7; j++)
#pragma unroll
        for (int k = 0; k < 4; k++) acc[j][k] = 0ull;

    int off = 0;
    for (int round = 0; round < 3; round++) {
        const int csz = (round < 2) ? 33 : 15;
        __syncthreads();   // previous Ws readers done (round 0: phase A done, Bs/As dead)
        // stage Ws dup-weights: Ws[(qq*33 + b)*62 + ig*8 + j] = {w,w}
        for (int idx = tid; idx < 4 * csz * L2DIM; idx += NTHR) {
            int qq  = idx / (csz * L2DIM);
            int rem = idx - qq * csz * L2DIM;
            int b   = rem / L2DIM;
            int i   = rem - b * L2DIM;
            int igi = i / 7, j = i - igi * 7;
            float wv = Wf[(size_t)(qq * 81 + off + b) * L2DIM + i];
            Ws[(qq * WS_CHUNK + b) * WS_STRIDE + igi * 8 + j] = pack2(wv);
        }
        __syncthreads();

        if (act) {
            const ull* wsq = Ws + (q * WS_CHUNK) * WS_STRIDE + ig * 8;
            const ull* gq  = G2s + (size_t)(q * 81 + off) * CP + cpb;
#pragma unroll 3
            for (int b = 0; b < csz; b++) {
                ulonglong2 w01 = *reinterpret_cast<const ulonglong2*>(wsq + b * WS_STRIDE);
                ulonglong2 w23 = *reinterpret_cast<const ulonglong2*>(wsq + b * WS_STRIDE + 2);
                ulonglong2 w45 = *reinterpret_cast<const ulonglong2*>(wsq + b * WS_STRIDE + 4);
                ull        w6  = wsq[b * WS_STRIDE + 6];
                ulonglong2 g01 = *reinterpret_cast<const ulonglong2*>(gq + (size_t)b * CP);
                ulonglong2 g23 = *reinterpret_cast<const ulonglong2*>(gq + (size_t)b * CP + 2);
                acc[0][0] = ffma2(w01.x, g01.x, acc[0][0]);
                acc[0][1] = ffma2(w01.x, g01.y, acc[0][1]);
                acc[0][2] = ffma2(w01.x, g23.x, acc[0][2]);
                acc[0][3] = ffma2(w01.x, g23.y, acc[0][3]);
                acc[1][0] = ffma2(w01.y, g01.x, acc[1][0]);
                acc[1][1] = ffma2(w01.y, g01.y, acc[1][1]);
                acc[1][2] = ffma2(w01.y, g23.x, acc[1][2]);
                acc[1][3] = ffma2(w01.y, g23.y, acc[1][3]);
                acc[2][0] = ffma2(w23.x, g01.x, acc[2][0]);
                acc[2][1] = ffma2(w23.x, g01.y, acc[2][1]);
                acc[2][2] = ffma2(w23.x, g23.x, acc[2][2]);
                acc[2][3] = ffma2(w23.x, g23.y, acc[2][3]);
                acc[3][0] = ffma2(w23.y, g01.x, acc[3][0]);
                acc[3][1] = ffma2(w23.y, g01.y, acc[3][1]);
                acc[3][2] = ffma2(w23.y, g23.x, acc[3][2]);
                acc[3][3] = ffma2(w23.y, g23.y, acc[3][3]);
                acc[4][0] = ffma2(w45.x, g01.x, acc[4][0]);
                acc[4][1] = ffma2(w45.x, g01.y, acc[4][1]);
                acc[4][2] = ffma2(w45.x, g23.x, acc[4][2]);
                acc[4][3] = ffma2(w45.x, g23.y, acc[4][3]);
                acc[5][0] = ffma2(w45.y, g01.x, acc[5][0]);
                acc[5][1] = ffma2(w45.y, g01.y, acc[5][1]);
                acc[5][2] = ffma2(w45.y, g23.x, acc[5][2]);
                acc[5][3] = ffma2(w45.y, g23.y, acc[5][3]);
                acc[6][0] = ffma2(w6, g01.x, acc[6][0]);
                acc[6][1] = ffma2(w6, g01.y, acc[6][1]);
                acc[6][2] = ffma2(w6, g23.x, acc[6][2]);
                acc[6][3] = ffma2(w6, g23.y, acc[6][3]);
            }
        }
        off += csz;
    }

    // ---------- Phase C: 4-way quarter reduction + writeout ----------
    __syncthreads();   // all G2s reads complete; reuse region for partials P[q][i][cp]
    ull* P = G2s;
    if (act) {
#pragma unroll
        for (int j = 0; j < 7; j++) {
            int i = ig * 7 + j;
            ulonglong2 a01, a23;
            a01.x = acc[j][0]; a01.y = acc[j][1];
            a23.x = acc[j][2]; a23.y = acc[j][3];
            *reinterpret_cast<ulonglong2*>(P + ((size_t)q * L2DIM + i) * CP + cpb)     = a01;
            *reinterpret_cast<ulonglong2*>(P + ((size_t)q * L2DIM + i) * CP + cpb + 2) = a23;
        }
    }
    __syncthreads();
    ull* outp = reinterpret_cast<ull*>(Out) + (size_t)n * L2DIM * CP;
    const int TOT = L2DIM * CP;   // 3136
    for (int idx = tid; idx < TOT; idx += NTHR) {
        ull s = fadd2(fadd2(P[idx], P[TOT + idx]),
                      fadd2(P[2 * TOT + idx], P[3 * TOT + idx]));
        outp[idx] = s;
    }
}

// ---------------- launcher ----------------
extern "C" void kernel_launch(void* const* d_in, const int* in_sizes, int n_in,
                              void* d_out, int out_size) {
    const float* X   = (const float*)d_in[0];  // inputs  (N, 49, 128)
    const float* Wto = (const float*)d_in[1];  // W_to    (18, 18, 49)
    const float* Wf  = (const float*)d_in[2];  // W_from  (18, 18, 49)
    float* Out = (float*)d_out;                // (N, 49, 128)

    static bool attr_set = false;
    if (!attr_set) {
        cudaFuncSetAttribute(fused_kernel,
                             cudaFuncAttributeMaxDynamicSharedMemorySize,
                             SMEM_BYTES);
        attr_set = true;
    }

    fused_kernel<<<NB, NTHR, SMEM_BYTES>>>(X, Wto, Wf, Out);
}

// round 9
// speedup vs baseline: 1.1689x; 1.1689x over previous
#include <cuda_runtime.h>
#include <cstdint>
#include <cstddef>

// Problem constants
#define NB    4096
#define L2DIM 49
#define CDIM  128
#define BAD   324
#define CP    64            // channel pairs (f32x2)
#define NTHR  512

typedef unsigned long long ull;

__device__ __forceinline__ ull ffma2(ull a, ull b, ull c) {
    ull d;
    asm("fma.rn.f32x2 %0, %1, %2, %3;" : "=l"(d) : "l"(a), "l"(b), "l"(c));
    return d;
}
__device__ __forceinline__ ull fmul2(ull a, ull b) {
    ull d;
    asm("mul.rn.f32x2 %0, %1, %2;" : "=l"(d) : "l"(a), "l"(b));
    return d;
}
__device__ __forceinline__ ull fadd2(ull a, ull b) {
    ull d;
    asm("add.rn.f32x2 %0, %1, %2;" : "=l"(d) : "l"(a), "l"(b));
    return d;
}
__device__ __forceinline__ ull pack2(float x) {
    ull d;
    asm("mov.b64 %0, {%1, %1};" : "=l"(d) : "f"(x));
    return d;
}

// ---------------- SMEM layout ----------------
// [0, 165888)   G2s ull[324][64]  (squared grid; later overlaid by P with stride 66)
// [165888, ...) region2:
//   phase A: Bs ull[49*64] (25088 B) @ +0 ; As2 float[256*27] (27648 B) @ +25088
//   phase B: Ws float[132*64] (33792 B) @ +0
#define R2_OFF     165888
#define AS_OFF     (R2_OFF + 25088)
#define AS_STR     27          // floats per row (conflict-free: 8*27 mod 32 = 24)
#define WS_STR     64          // floats per (qq,b) row
#define P_STR      66          // ull stride for partials (kills STS conflicts)
#define SMEM_BYTES (AS_OFF + 27648 - 0)   // 218624

__global__ void __launch_bounds__(NTHR, 1)
fused_kernel(const float* __restrict__ X,
             const float* __restrict__ Wto,
             const float* __restrict__ Wf,
             float* __restrict__ Out) {
    extern __shared__ __align__(16) char smem[];
    ull*   G2s = reinterpret_cast<ull*>(smem);
    ull*   Bs  = reinterpret_cast<ull*>(smem + R2_OFF);
    float* As2 = reinterpret_cast<float*>(smem + AS_OFF);
    float* Ws  = reinterpret_cast<float*>(smem + R2_OFF);

    const int n    = blockIdx.x;
    const int tid  = threadIdx.x;
    const int wrp  = tid >> 5;
    const int lane = tid & 31;

    // Phase A roles: warp covers 16 rows x 64 cp; lane = (rg 0..1, cl 0..15)
    const int rg = lane >> 4;
    const int cl = lane & 15;

    // ---------- stage Bs: x[n] (float4 coalesced, conflict-free) ----------
    {
        const float4* Xv = reinterpret_cast<const float4*>(X + (size_t)n * L2DIM * CDIM);
        float4* Bv = reinterpret_cast<float4*>(Bs);
        for (int idx = tid; idx < L2DIM * 32; idx += NTHR) Bv[idx] = Xv[idx];
    }

    // ================= Phase A: G2s = (W_to @ x)^2 =================
    for (int chunk = 0; chunk < 2; chunk++) {
        const int  cbase  = chunk * 256;
        const int  nslots = chunk ? 5 : 16;
        const bool active = (wrp < nslots);
        const int  rbase  = wrp * 16 + rg * 8;    // local row base within chunk

        ull acc[8][4];
#pragma unroll
        for (int d = 0; d < 8; d++)
#pragma unroll
            for (int k = 0; k < 4; k++) acc[d][k] = 0ull;

#pragma unroll
        for (int ihalf = 0; ihalf < 2; ihalf++) {
            const int ioff = ihalf * 25;
            const int icnt = 25 - ihalf;          // 25 then 24
            __syncthreads();
            // stage As2[r][ii] = Wto[(cbase+r)][ioff+ii]  (coalesced LDG, conflict-free STS)
            for (int r = wrp; r < 256; r += 16) {
                if (lane < icnt) {
                    int grow = cbase + r;
                    float v = (grow < BAD) ? Wto[(size_t)grow * L2DIM + ioff + lane] : 0.0f;
                    As2[r * AS_STR + lane] = v;
                }
            }
            __syncthreads();

            if (active) {
                const float* wp = As2 + rbase * AS_STR;
                const ull*   xp = Bs + (size_t)ioff * CP + cl * 2;
#pragma unroll 5
                for (int ii = 0; ii < icnt; ii++) {
                    ull w[8];
#pragma unroll
                    for (int d = 0; d < 8; d++) w[d] = pack2(wp[d * AS_STR + ii]);
                    ulonglong2 xa = *reinterpret_cast<const ulonglong2*>(xp + (size_t)ii * CP);
                    ulonglong2 xb = *reinterpret_cast<const ulonglong2*>(xp + (size_t)ii * CP + 32);
#pragma unroll
                    for (int d = 0; d < 8; d++) {
                        acc[d][0] = ffma2(w[d], xa.x, acc[d][0]);
                        acc[d][1] = ffma2(w[d], xa.y, acc[d][1]);
                        acc[d][2] = ffma2(w[d], xb.x, acc[d][2]);
                        acc[d][3] = ffma2(w[d], xb.y, acc[d][3]);
                    }
                }
            }
        }

        // square & store (conflict-free: cl*2 contiguous within phase)
        if (active) {
#pragma unroll
            for (int d = 0; d < 8; d++) {
                int row = cbase + rbase + d;
                if (row < BAD) {
                    ulonglong2 v0, v1;
                    v0.x = fmul2(acc[d][0], acc[d][0]);
                    v0.y = fmul2(acc[d][1], acc[d][1]);
                    v1.x = fmul2(acc[d][2], acc[d][2]);
                    v1.y = fmul2(acc[d][3], acc[d][3]);
                    *reinterpret_cast<ulonglong2*>(G2s + (size_t)row * CP + cl * 2)      = v0;
                    *reinterpret_cast<ulonglong2*>(G2s + (size_t)row * CP + 32 + cl * 2) = v1;
                }
            }
        }
    }

    // ================= Phase B: out = W_from^T @ G2 =================
    // warp = (quarter q, cgroup cgw); lane<28 = (ig 0..6, clb 0..3)
    const int  q   = wrp >> 2;
    const int  cgw = wrp & 3;
    const int  ig  = lane >> 2;
    const int  clb = lane & 3;
    const bool act = (lane < 28);

    ull accB[7][4];
#pragma unroll
    for (int j = 0; j < 7; j++)
#pragma unroll
        for (int k = 0; k < 4; k++) accB[j][k] = 0ull;

    int off = 0;
    for (int round = 0; round < 3; round++) {
        const int csz = (round < 2) ? 33 : 15;
        __syncthreads();
        // stage Ws[(qq*33+b)][ig*8+j] = Wf[(qq*81+off+b)][ig*7+j]
        for (int rr = wrp; rr < 4 * csz; rr += 16) {
            int qq = rr / csz;
            int b  = rr - qq * csz;
            const float* src = Wf + (size_t)(qq * 81 + off + b) * L2DIM;
            float* dst = Ws + (qq * 33 + b) * WS_STR;
            {
                int i = lane;
                if (i < L2DIM) dst[(i / 7) * 8 + (i % 7)] = src[i];
                i = lane + 32;
                if (i < L2DIM) dst[(i / 7) * 8 + (i % 7)] = src[i];
            }
        }
        __syncthreads();

        if (act) {
            const float* wsq = Ws + (q * 33) * WS_STR + ig * 8;
            const ull*   gq  = G2s + (size_t)(q * 81 + off) * CP + cgw * 16 + clb * 4;
#pragma unroll 3
            for (int b = 0; b < csz; b++) {
                float2 wa = *reinterpret_cast<const float2*>(wsq + b * WS_STR);
                float2 wb = *reinterpret_cast<const float2*>(wsq + b * WS_STR + 2);
                float2 wc = *reinterpret_cast<const float2*>(wsq + b * WS_STR + 4);
                float  wd = wsq[b * WS_STR + 6];
                ull w0 = pack2(wa.x), w1 = pack2(wa.y), w2 = pack2(wb.x);
                ull w3 = pack2(wb.y), w4 = pack2(wc.x), w5 = pack2(wc.y);
                ull w6 = pack2(wd);
                ulonglong2 g01 = *reinterpret_cast<const ulonglong2*>(gq + (size_t)b * CP);
                ulonglong2 g23 = *reinterpret_cast<const ulonglong2*>(gq + (size_t)b * CP + 2);
                accB[0][0] = ffma2(w0, g01.x, accB[0][0]);
                accB[0][1] = ffma2(w0, g01.y, accB[0][1]);
                accB[0][2] = ffma2(w0, g23.x, accB[0][2]);
                accB[0][3] = ffma2(w0, g23.y, accB[0][3]);
                accB[1][0] = ffma2(w1, g01.x, accB[1][0]);
                accB[1][1] = ffma2(w1, g01.y, accB[1][1]);
                accB[1][2] = ffma2(w1, g23.x, accB[1][2]);
                accB[1][3] = ffma2(w1, g23.y, accB[1][3]);
                accB[2][0] = ffma2(w2, g01.x, accB[2][0]);
                accB[2][1] = ffma2(w2, g01.y, accB[2][1]);
                accB[2][2] = ffma2(w2, g23.x, accB[2][2]);
                accB[2][3] = ffma2(w2, g23.y, accB[2][3]);
                accB[3][0] = ffma2(w3, g01.x, accB[3][0]);
                accB[3][1] = ffma2(w3, g01.y, accB[3][1]);
                accB[3][2] = ffma2(w3, g23.x, accB[3][2]);
                accB[3][3] = ffma2(w3, g23.y, accB[3][3]);
                accB[4][0] = ffma2(w4, g01.x, accB[4][0]);
                accB[4][1] = ffma2(w4, g01.y, accB[4][1]);
                accB[4][2] = ffma2(w4, g23.x, accB[4][2]);
                accB[4][3] = ffma2(w4, g23.y, accB[4][3]);
                accB[5][0] = ffma2(w5, g01.x, accB[5][0]);
                accB[5][1] = ffma2(w5, g01.y, accB[5][1]);
                accB[5][2] = ffma2(w5, g23.x, accB[5][2]);
                accB[5][3] = ffma2(w5, g23.y, accB[5][3]);
                accB[6][0] = ffma2(w6, g01.x, accB[6][0]);
                accB[6][1] = ffma2(w6, g01.y, accB[6][1]);
                accB[6][2] = ffma2(w6, g23.x, accB[6][2]);
                accB[6][3] = ffma2(w6, g23.y, accB[6][3]);
            }
        }
        off += csz;
    }

    // ---------- Phase C: 4-way quarter reduction + writeout ----------
    __syncthreads();   // all G2s reads done; overlay P (stride 66, conflict-free)
    ull* P = G2s;
    if (act) {
#pragma unroll
        for (int j = 0; j < 7; j++) {
            int i = ig * 7 + j;
            ulonglong2 a01, a23;
            a01.x = accB[j][0]; a01.y = accB[j][1];
            a23.x = accB[j][2]; a23.y = accB[j][3];
            ull* pb = P + (size_t)(q * L2DIM + i) * P_STR + cgw * 16 + clb * 4;
            *reinterpret_cast<ulonglong2*>(pb)     = a01;
            *reinterpret_cast<ulonglong2*>(pb + 2) = a23;
        }
    }
    __syncthreads();
    ull* outp = reinterpret_cast<ull*>(Out) + (size_t)n * L2DIM * CP;
    for (int idx = tid; idx < L2DIM * CP; idx += NTHR) {
        int i = idx >> 6;
        int c = idx & 63;
        ull s = fadd2(
            fadd2(P[(size_t)i * P_STR + c],
                  P[(size_t)(L2DIM + i) * P_STR + c]),
            fadd2(P[(size_t)(2 * L2DIM + i) * P_STR + c],
                  P[(size_t)(3 * L2DIM + i) * P_STR + c]));
        outp[idx] = s;
    }
}

// ---------------- launcher ----------------
extern "C" void kernel_launch(void* const* d_in, const int* in_sizes, int n_in,
                              void* d_out, int out_size) {
    const float* X   = (const float*)d_in[0];  // inputs  (N, 49, 128)
    const float* Wto = (const float*)d_in[1];  // W_to    (18, 18, 49)
    const float* Wf  = (const float*)d_in[2];  // W_from  (18, 18, 49)
    float* Out = (float*)d_out;                // (N, 49, 128)

    static bool attr_set = false;
    if (!attr_set) {
        cudaFuncSetAttribute(fused_kernel,
                             cudaFuncAttributeMaxDynamicSharedMemorySize,
                             SMEM_BYTES);
        attr_set = true;
    }

    fused_kernel<<<NB, NTHR, SMEM_BYTES>>>(X, Wto, Wf, Out);
}